// round 16
// baseline (speedup 1.0000x reference)
#include <cuda_runtime.h>
#include <cstdint>

#define NSIDE    48
#define NPIX     2304          // 48*48
#define LDW      52            // padded smem row stride (floats)
#define NTHREADS 96            // 3 warps; warp tile 24x16, thread 3 rows x 4 cols
#define NWARPS   3
#define ROWS_PER_CTA 24
#define INV_EPS  100.0f
#define MAXB     64

__device__ float g_cost[MAXB];
__device__ unsigned int g_count = 0;

typedef unsigned long long u64t;

__device__ __forceinline__ float4 ld4(const float* p) {
    return *reinterpret_cast<const float4*>(p);
}
__device__ __forceinline__ void st4(float* p, float4 v) {
    *reinterpret_cast<float4*>(p) = v;
}
__device__ __forceinline__ float mass_of(float x) {
    return fminf(fmaxf(x, 0.0f), 1e9f) + 1e-9f;
}

// ---- packed f32x2 helpers --------------------------------------------------
__device__ __forceinline__ u64t pack2(float v) {
    u64t r; asm("mov.b64 %0, {%1, %1};" : "=l"(r) : "f"(v)); return r;
}
__device__ __forceinline__ u64t ffma2(u64t a, u64t b, u64t c) {
    u64t d; asm("fma.rn.f32x2 %0, %1, %2, %3;" : "=l"(d) : "l"(a), "l"(b), "l"(c));
    return d;
}
__device__ __forceinline__ float2 unpack2(u64t v) {
    float2 f; asm("mov.b64 {%0, %1}, %2;" : "=f"(f.x), "=f"(f.y) : "l"(v));
    return f;
}

// ---- cluster helpers -------------------------------------------------------
__device__ __forceinline__ uint32_t ctarank() {
    uint32_t r; asm("mov.u32 %0, %%cluster_ctarank;" : "=r"(r)); return r;
}
__device__ __forceinline__ uint32_t smem_u32(const void* p) {
    return (uint32_t)__cvta_generic_to_shared(p);
}
// store float4 into the SAME smem offset of a peer CTA in the cluster
__device__ __forceinline__ void st_peer4(uint32_t laddr, uint32_t peer, float4 v) {
    uint32_t ra;
    asm("mapa.shared::cluster.u32 %0, %1, %2;" : "=r"(ra) : "r"(laddr), "r"(peer));
    asm volatile("st.shared::cluster.v4.f32 [%0], {%1, %2, %3, %4};"
                 :: "r"(ra), "f"(v.x), "f"(v.y), "f"(v.z), "f"(v.w) : "memory");
}
#define CLUSTER_SYNC() do { \
    asm volatile("barrier.cluster.arrive.aligned;" ::: "memory"); \
    asm volatile("barrier.cluster.wait.aligned;"   ::: "memory"); \
} while (0)

// ---------------------------------------------------------------------------
// block reduce (all threads receive the sum; deterministic order)
// ---------------------------------------------------------------------------
__device__ __forceinline__ float block_reduce(float val, float* red) {
#pragma unroll
    for (int o = 16; o; o >>= 1) val += __shfl_down_sync(0xffffffffu, val, o);
    if ((threadIdx.x & 31) == 0) red[threadIdx.x >> 5] = val;
    __syncthreads();
    float s = red[0];
#pragma unroll
    for (int w = 1; w < NWARPS; w++) s += red[w];
    __syncthreads();
    return s;
}

// ---------------------------------------------------------------------------
// Dense 48-col matmul slice, thread = 3 rows x 4 cols, software-pipelined.
// A rows indexed globally (r0 = this CTA's slice); B full 48 rows.
// ---------------------------------------------------------------------------
__device__ __forceinline__ void mm_wb(const float* __restrict__ A,
                                      const float* __restrict__ B,
                                      int r0, int c0, u64t acc[3][2]) {
#pragma unroll
    for (int i = 0; i < 3; i++) { acc[i][0] = 0ull; acc[i][1] = 0ull; }
    const float* a0p = A + r0 * LDW;
    const float* a1p = a0p + LDW;
    const float* a2p = a1p + LDW;
    const float* bp  = B + c0;

    float4 av0 = ld4(a0p);
    float4 av1 = ld4(a1p);
    float4 av2 = ld4(a2p);
    ulonglong2 b0 = *reinterpret_cast<const ulonglong2*>(bp);
    ulonglong2 b1 = *reinterpret_cast<const ulonglong2*>(bp + LDW);
    ulonglong2 b2 = *reinterpret_cast<const ulonglong2*>(bp + 2 * LDW);
    ulonglong2 b3 = *reinterpret_cast<const ulonglong2*>(bp + 3 * LDW);

#pragma unroll
    for (int ch = 0; ch < 12; ch++) {
        float4 ca0 = av0, ca1 = av1, ca2 = av2;
        ulonglong2 cb0 = b0, cb1 = b1, cb2 = b2, cb3 = b3;
        if (ch < 11) {
            int nb = (ch + 1) * 4;
            av0 = ld4(a0p + nb);
            av1 = ld4(a1p + nb);
            av2 = ld4(a2p + nb);
            const float* nbp = bp + nb * LDW;
            b0 = *reinterpret_cast<const ulonglong2*>(nbp);
            b1 = *reinterpret_cast<const ulonglong2*>(nbp + LDW);
            b2 = *reinterpret_cast<const ulonglong2*>(nbp + 2 * LDW);
            b3 = *reinterpret_cast<const ulonglong2*>(nbp + 3 * LDW);
        }
        u64t pa;
        pa = pack2(ca0.x); acc[0][0] = ffma2(pa, cb0.x, acc[0][0]); acc[0][1] = ffma2(pa, cb0.y, acc[0][1]);
        pa = pack2(ca1.x); acc[1][0] = ffma2(pa, cb0.x, acc[1][0]); acc[1][1] = ffma2(pa, cb0.y, acc[1][1]);
        pa = pack2(ca2.x); acc[2][0] = ffma2(pa, cb0.x, acc[2][0]); acc[2][1] = ffma2(pa, cb0.y, acc[2][1]);
        pa = pack2(ca0.y); acc[0][0] = ffma2(pa, cb1.x, acc[0][0]); acc[0][1] = ffma2(pa, cb1.y, acc[0][1]);
        pa = pack2(ca1.y); acc[1][0] = ffma2(pa, cb1.x, acc[1][0]); acc[1][1] = ffma2(pa, cb1.y, acc[1][1]);
        pa = pack2(ca2.y); acc[2][0] = ffma2(pa, cb1.x, acc[2][0]); acc[2][1] = ffma2(pa, cb1.y, acc[2][1]);
        pa = pack2(ca0.z); acc[0][0] = ffma2(pa, cb2.x, acc[0][0]); acc[0][1] = ffma2(pa, cb2.y, acc[0][1]);
        pa = pack2(ca1.z); acc[1][0] = ffma2(pa, cb2.x, acc[1][0]); acc[1][1] = ffma2(pa, cb2.y, acc[1][1]);
        pa = pack2(ca2.z); acc[2][0] = ffma2(pa, cb2.x, acc[2][0]); acc[2][1] = ffma2(pa, cb2.y, acc[2][1]);
        pa = pack2(ca0.w); acc[0][0] = ffma2(pa, cb3.x, acc[0][0]); acc[0][1] = ffma2(pa, cb3.y, acc[0][1]);
        pa = pack2(ca1.w); acc[1][0] = ffma2(pa, cb3.x, acc[1][0]); acc[1][1] = ffma2(pa, cb3.y, acc[1][1]);
        pa = pack2(ca2.w); acc[2][0] = ffma2(pa, cb3.x, acc[2][0]); acc[2][1] = ffma2(pa, cb3.y, acc[2][1]);
    }
}

__device__ __forceinline__ void st_acc(float* dst, u64t acc0, u64t acc1) {
    ulonglong2 v; v.x = acc0; v.y = acc1;
    *reinterpret_cast<ulonglong2*>(dst) = v;
}

// ---------------------------------------------------------------------------
// 2-CTA cluster per batch image. CTA rank r owns output rows [r*24, r*24+24).
// Scalings a/b are replicated in both CTAs' smem (DSMEM writes on update);
// the T intermediate stays CTA-local. Multiplicative-domain Sinkhorn:
//   a <- mu*a/(a*(K b K) + 1e-6), b <- nu*b/(b*(K a K) + 1e-6)
// identical to the reference log-domain update with non-shifted lse +1e-6.
// ---------------------------------------------------------------------------
__global__ __launch_bounds__(NTHREADS) __cluster_dims__(2, 1, 1)
void sinkhorn_kernel(const float* __restrict__ y, const float* __restrict__ yt,
                     float* __restrict__ out, int nb) {
    __shared__ __align__(16) float sK[NSIDE * LDW];
    __shared__ __align__(16) float sA[NSIDE * LDW];   // replicated scaling a
    __shared__ __align__(16) float sB[NSIDE * LDW];   // replicated scaling b
    __shared__ __align__(16) float sT[NSIDE * LDW];   // local temp (own rows)
    __shared__ float ktab[NSIDE];
    __shared__ float kdtab[NSIDE];
    __shared__ float red[NWARPS];

    const int tid  = threadIdx.x;
    const int wid  = tid >> 5;               // 0..2 -> col block
    const int lane = tid & 31;
    const int lr   = lane >> 2;              // row slot 0..7
    const int lc   = lane & 3;               // col slot 0..3
    const uint32_t rank = ctarank();         // 0/1
    const uint32_t peer = 1u - rank;
    const int img  = blockIdx.x >> 1;
    const int r0   = (int)rank * ROWS_PER_CTA + lr * 3;  // global rows r0..r0+2
    const int c0   = wid * 16 + lc * 4;

    const float* yb  = y  + (size_t)img * NPIX;
    const float* ytb = yt + (size_t)img * NPIX;

    if (tid < NSIDE) {
        float dd = (float)tid * (1.0f / 48.0f);
        float d2 = dd * dd;
        float k  = expf(-d2 * INV_EPS);
        ktab[tid]  = k;
        kdtab[tid] = k * d2;
    }
    for (int i = tid; i < NPIX; i += NTHREADS) {
        int ro = i / NSIDE, co = i % NSIDE;
        int d  = ro - co; d = d < 0 ? -d : d;
        float dd = (float)d * (1.0f / 48.0f);
        sK[ro * LDW + co] = expf(-dd * dd * INV_EPS);
        sA[ro * LDW + co] = 1.0f;            // full local replicas init to 1
        sB[ro * LDW + co] = 1.0f;
    }

    // full-image mass sums (each CTA computes independently from gmem/L2)
    float sxl = 0.0f, syl = 0.0f;
    for (int i = tid; i < NPIX; i += NTHREADS) {
        sxl += mass_of(yb[i]);
        syl += mass_of(ytb[i]);
    }
    __syncthreads();
    const float sx = block_reduce(sxl, red);
    const float sy = block_reduce(syl, red);
    const float rsx = 1.0f / sx, rsy = 1.0f / sy;

    float4 mu4[3], nu4[3], a4[3], b4[3];
#pragma unroll
    for (int i = 0; i < 3; i++) {
        int gidx = (r0 + i) * NSIDE + c0;
        float4 yv  = ld4(yb  + gidx);
        float4 ytv = ld4(ytb + gidx);
        mu4[i] = make_float4(mass_of(yv.x) * rsx, mass_of(yv.y) * rsx,
                             mass_of(yv.z) * rsx, mass_of(yv.w) * rsx);
        nu4[i] = make_float4(mass_of(ytv.x) * rsy, mass_of(ytv.y) * rsy,
                             mass_of(ytv.z) * rsy, mass_of(ytv.w) * rsy);
        a4[i] = make_float4(1.f, 1.f, 1.f, 1.f);
        b4[i] = make_float4(1.f, 1.f, 1.f, 1.f);
    }
    __syncthreads();
    CLUSTER_SYNC();    // peer's replicas initialized before any DSMEM write

    // 5 Sinkhorn iterations; u-update (h=0) and v-update (h=1) share one body.
    u64t t[3][2], s[3][2];
#pragma unroll 1
    for (int it = 0; it < 5; it++) {
#pragma unroll 1
        for (int h = 0; h < 2; h++) {
            const float* X = h ? sA : sB;    // operand (replicated, stable)
            float* D       = h ? sB : sA;    // destination scalings
            mm_wb(sK, X, r0, c0, t);         // T[own rows, :] = K*X
#pragma unroll
            for (int i = 0; i < 3; i++)
                st_acc(&sT[(r0 + i) * LDW + c0], t[i][0], t[i][1]);
            __syncthreads();
            mm_wb(sT, sK, r0, c0, s);        // S[own rows, :] = T*K
#pragma unroll
            for (int i = 0; i < 3; i++) {
                float4 mv = h ? nu4[i] : mu4[i];
                float4 xv = h ? b4[i]  : a4[i];
                float2 slo = unpack2(s[i][0]);
                float2 shi = unpack2(s[i][1]);
                float4 nx;
                nx.x = __fdividef(mv.x * xv.x, fmaf(xv.x, slo.x, 1e-6f));
                nx.y = __fdividef(mv.y * xv.y, fmaf(xv.y, slo.y, 1e-6f));
                nx.z = __fdividef(mv.z * xv.z, fmaf(xv.z, shi.x, 1e-6f));
                nx.w = __fdividef(mv.w * xv.w, fmaf(xv.w, shi.y, 1e-6f));
                if (h) b4[i] = nx; else a4[i] = nx;
                float* dst = &D[(r0 + i) * LDW + c0];
                st4(dst, nx);                          // local replica
                st_peer4(smem_u32(dst), peer, nx);     // peer replica (DSMEM)
            }
            CLUSTER_SYNC();   // replication visible before next matmul
        }
    }

    // cost = sum_i a_i * [ (KD*B*K) + (K*B*KD) ]_i over own rows.
    // Pass 1: T1 = KD*B (-> sT own rows), T2 = K*B (-> sA own rows, local).
    {
        float4 t1[3], t2[3];
#pragma unroll
        for (int i = 0; i < 3; i++) {
            t1[i] = make_float4(0.f, 0.f, 0.f, 0.f);
            t2[i] = make_float4(0.f, 0.f, 0.f, 0.f);
        }
#pragma unroll 8
        for (int b = 0; b < NSIDE; b++) {
            float4 bv = ld4(sB + b * LDW + c0);
#pragma unroll
            for (int i = 0; i < 3; i++) {
                int d0 = r0 + i - b; d0 = d0 < 0 ? -d0 : d0;
                float kd = kdtab[d0];
                float kk = ktab[d0];
                t1[i].x = fmaf(kd, bv.x, t1[i].x); t1[i].y = fmaf(kd, bv.y, t1[i].y);
                t1[i].z = fmaf(kd, bv.z, t1[i].z); t1[i].w = fmaf(kd, bv.w, t1[i].w);
                t2[i].x = fmaf(kk, bv.x, t2[i].x); t2[i].y = fmaf(kk, bv.y, t2[i].y);
                t2[i].z = fmaf(kk, bv.z, t2[i].z); t2[i].w = fmaf(kk, bv.w, t2[i].w);
            }
        }
        __syncthreads();
#pragma unroll
        for (int i = 0; i < 3; i++) {
            st4(&sT[(r0 + i) * LDW + c0], t1[i]);
            st4(&sA[(r0 + i) * LDW + c0], t2[i]);
        }
        __syncthreads();
    }

    // Pass 2: S1 = T1*K, S2 = T2*KD; cl = sum a .* (S1 + S2) over own rows
    float cl = 0.0f;
    {
        float4 s1[3], s2[3];
#pragma unroll
        for (int i = 0; i < 3; i++) {
            s1[i] = make_float4(0.f, 0.f, 0.f, 0.f);
            s2[i] = make_float4(0.f, 0.f, 0.f, 0.f);
        }
#pragma unroll 8
        for (int b = 0; b < NSIDE; b++) {
            float4 kv = ld4(sK + b * LDW + c0);
            int e0 = b - c0;     e0 = e0 < 0 ? -e0 : e0;
            int e1 = b - c0 - 1; e1 = e1 < 0 ? -e1 : e1;
            int e2 = b - c0 - 2; e2 = e2 < 0 ? -e2 : e2;
            int e3 = b - c0 - 3; e3 = e3 < 0 ? -e3 : e3;
            float kd0 = kdtab[e0], kd1 = kdtab[e1], kd2 = kdtab[e2], kd3 = kdtab[e3];
#pragma unroll
            for (int i = 0; i < 3; i++) {
                float p0 = sT[(r0 + i) * LDW + b];
                float q0 = sA[(r0 + i) * LDW + b];
                s1[i].x = fmaf(p0, kv.x, s1[i].x); s1[i].y = fmaf(p0, kv.y, s1[i].y);
                s1[i].z = fmaf(p0, kv.z, s1[i].z); s1[i].w = fmaf(p0, kv.w, s1[i].w);
                s2[i].x = fmaf(q0, kd0, s2[i].x);  s2[i].y = fmaf(q0, kd1, s2[i].y);
                s2[i].z = fmaf(q0, kd2, s2[i].z);  s2[i].w = fmaf(q0, kd3, s2[i].w);
            }
        }
#pragma unroll
        for (int i = 0; i < 3; i++) {
            cl += a4[i].x * (s1[i].x + s2[i].x);
            cl += a4[i].y * (s1[i].y + s2[i].y);
            cl += a4[i].z * (s1[i].z + s2[i].z);
            cl += a4[i].w * (s1[i].w + s2[i].w);
        }
    }

    float c = block_reduce(cl, red);

    // per-CTA partial; last of the 2*nb CTAs computes mean (replay-safe reset)
    if (tid == 0) {
        g_cost[blockIdx.x] = c;
        __threadfence();
        unsigned done = atomicAdd(&g_count, 1u);
        if (done == (unsigned)(2 * nb - 1)) {
            float ssum = 0.0f;
            for (int i = 0; i < 2 * nb; i++) ssum += g_cost[i];
            *out = ssum / (float)nb;
            g_count = 0;
        }
    }
}

extern "C" void kernel_launch(void* const* d_in, const int* in_sizes, int n_in,
                              void* d_out, int out_size) {
    const float* y  = (const float*)d_in[0];
    const float* yt = (const float*)d_in[1];
    float* out = (float*)d_out;

    int nb = in_sizes[0] / NPIX;   // 16
    if (nb < 1)  nb = 1;
    if (nb > MAXB / 2) nb = MAXB / 2;

    sinkhorn_kernel<<<2 * nb, NTHREADS>>>(y, yt, out, nb);
}

// round 17
// speedup vs baseline: 1.1107x; 1.1107x over previous
#include <cuda_runtime.h>

#define NSIDE    48
#define NPIX     2304          // 48*48
#define LDW      52            // normal smem row stride (floats)
#define LDW2     100           // doubled-layout row stride (floats)
#define NTHREADS 192           // 6 warps: 2x3 grid of 24x16 warp tiles
#define NWARPS   6
#define INV_EPS  100.0f
#define MAXB     64

// dynamic smem layout (floats); every offset is 128B-aligned
#define OFF_K    0             // normal K           (48*52  = 2496)
#define OFF_A    2496          // scaling a (normal)
#define OFF_B    4992          // scaling b (normal)
#define OFF_K2   7488          // doubled K          (48*100 = 4800)
#define OFF_T2   12288         // doubled T / scratch
#define DYN_FLOATS 17088
#define DYN_BYTES  (DYN_FLOATS * 4)

__device__ float g_cost[MAXB];
__device__ unsigned int g_count = 0;

typedef unsigned long long u64t;

__device__ __forceinline__ float4 ld4(const float* p) {
    return *reinterpret_cast<const float4*>(p);
}
__device__ __forceinline__ void st4(float* p, float4 v) {
    *reinterpret_cast<float4*>(p) = v;
}
__device__ __forceinline__ float mass_of(float x) {
    return fminf(fmaxf(x, 0.0f), 1e9f) + 1e-9f;
}
__device__ __forceinline__ u64t ffma2(u64t a, u64t b, u64t c) {
    u64t d; asm("fma.rn.f32x2 %0, %1, %2, %3;" : "=l"(d) : "l"(a), "l"(b), "l"(c));
    return d;
}
__device__ __forceinline__ float2 unpack2(u64t v) {
    float2 f; asm("mov.b64 {%0, %1}, %2;" : "=f"(f.x), "=f"(f.y) : "l"(v));
    return f;
}

// ---------------------------------------------------------------------------
// block reduce (all threads receive the sum; deterministic order)
// ---------------------------------------------------------------------------
__device__ __forceinline__ float block_reduce(float val, float* red) {
#pragma unroll
    for (int o = 16; o; o >>= 1) val += __shfl_down_sync(0xffffffffu, val, o);
    if ((threadIdx.x & 31) == 0) red[threadIdx.x >> 5] = val;
    __syncthreads();
    float s = red[0];
#pragma unroll
    for (int w = 1; w < NWARPS; w++) s += red[w];
    __syncthreads();
    return s;
}

// ---------------------------------------------------------------------------
// Banded dense matmul slice with DOUBLED A layout (A2[r][2b]=A2[r][2b+1]):
// thread = 3 rows x 4 cols; per chunk: 6 A-LDS.128 (ready f32x2 operands,
// no packing) + 4 B-LDS.128 + 24 FFMA2. Chunk range [CHLO, CHHI) is the
// warp-uniform Gaussian band (K(d)<4e-6 for |d|>=17 is dropped).
// ---------------------------------------------------------------------------
template <int CHLO, int CHHI>
__device__ __forceinline__ void mm_d(const float* __restrict__ A2,
                                     const float* __restrict__ B,
                                     int r0, int c0, u64t acc[3][2]) {
#pragma unroll
    for (int i = 0; i < 3; i++) { acc[i][0] = 0ull; acc[i][1] = 0ull; }
    const float* a0p = A2 + r0 * LDW2;
    const float* a1p = a0p + LDW2;
    const float* a2p = a1p + LDW2;
    const float* bp  = B + c0;
#pragma unroll
    for (int ch = CHLO; ch < CHHI; ch++) {
        const int db = 8 * ch;                 // doubled float offset of k=4ch
        ulonglong2 a0lo = *reinterpret_cast<const ulonglong2*>(a0p + db);
        ulonglong2 a0hi = *reinterpret_cast<const ulonglong2*>(a0p + db + 4);
        ulonglong2 a1lo = *reinterpret_cast<const ulonglong2*>(a1p + db);
        ulonglong2 a1hi = *reinterpret_cast<const ulonglong2*>(a1p + db + 4);
        ulonglong2 a2lo = *reinterpret_cast<const ulonglong2*>(a2p + db);
        ulonglong2 a2hi = *reinterpret_cast<const ulonglong2*>(a2p + db + 4);
        const float* bb = bp + 4 * ch * LDW;
        ulonglong2 b0 = *reinterpret_cast<const ulonglong2*>(bb);
        ulonglong2 b1 = *reinterpret_cast<const ulonglong2*>(bb + LDW);
        ulonglong2 b2 = *reinterpret_cast<const ulonglong2*>(bb + 2 * LDW);
        ulonglong2 b3 = *reinterpret_cast<const ulonglong2*>(bb + 3 * LDW);

        acc[0][0] = ffma2(a0lo.x, b0.x, acc[0][0]); acc[0][1] = ffma2(a0lo.x, b0.y, acc[0][1]);
        acc[1][0] = ffma2(a1lo.x, b0.x, acc[1][0]); acc[1][1] = ffma2(a1lo.x, b0.y, acc[1][1]);
        acc[2][0] = ffma2(a2lo.x, b0.x, acc[2][0]); acc[2][1] = ffma2(a2lo.x, b0.y, acc[2][1]);
        acc[0][0] = ffma2(a0lo.y, b1.x, acc[0][0]); acc[0][1] = ffma2(a0lo.y, b1.y, acc[0][1]);
        acc[1][0] = ffma2(a1lo.y, b1.x, acc[1][0]); acc[1][1] = ffma2(a1lo.y, b1.y, acc[1][1]);
        acc[2][0] = ffma2(a2lo.y, b1.x, acc[2][0]); acc[2][1] = ffma2(a2lo.y, b1.y, acc[2][1]);
        acc[0][0] = ffma2(a0hi.x, b2.x, acc[0][0]); acc[0][1] = ffma2(a0hi.x, b2.y, acc[0][1]);
        acc[1][0] = ffma2(a1hi.x, b2.x, acc[1][0]); acc[1][1] = ffma2(a1hi.x, b2.y, acc[1][1]);
        acc[2][0] = ffma2(a2hi.x, b2.x, acc[2][0]); acc[2][1] = ffma2(a2hi.x, b2.y, acc[2][1]);
        acc[0][0] = ffma2(a0hi.y, b3.x, acc[0][0]); acc[0][1] = ffma2(a0hi.y, b3.y, acc[0][1]);
        acc[1][0] = ffma2(a1hi.y, b3.x, acc[1][0]); acc[1][1] = ffma2(a1hi.y, b3.y, acc[1][1]);
        acc[2][0] = ffma2(a2hi.y, b3.x, acc[2][0]); acc[2][1] = ffma2(a2hi.y, b3.y, acc[2][1]);
    }
}

// write acc pairs into the DOUBLED layout (each scalar duplicated)
__device__ __forceinline__ void st_doubled(float* dst, u64t acc0, u64t acc1) {
    float2 lo = unpack2(acc0);
    float2 hi = unpack2(acc1);
    st4(dst,     make_float4(lo.x, lo.x, lo.y, lo.y));
    st4(dst + 4, make_float4(hi.x, hi.x, hi.y, hi.y));
}

extern __shared__ float dyn[];

// ---------------------------------------------------------------------------
// One CTA per batch image. Multiplicative-domain Sinkhorn:
//   a <- mu*a/(a*(K b K) + 1e-6), b <- nu*b/(b*(K a K) + 1e-6)
// identical to the reference log-domain update with non-shifted lse +1e-6.
// A-operands (K, T) live in doubled layout so FFMA2 needs no packing.
// ---------------------------------------------------------------------------
__global__ __launch_bounds__(NTHREADS)
void sinkhorn_kernel(const float* __restrict__ y, const float* __restrict__ yt,
                     float* __restrict__ out, int nb) {
    float* sK  = dyn + OFF_K;    // normal K (B operand / cost)
    float* sA  = dyn + OFF_A;    // scaling a (normal)
    float* sB  = dyn + OFF_B;    // scaling b (normal)
    float* sK2 = dyn + OFF_K2;   // doubled K (A operand)
    float* sT2 = dyn + OFF_T2;   // doubled T; cost-phase normal scratch

    __shared__ float ktab[NSIDE];
    __shared__ float kdtab[NSIDE];
    __shared__ float red[NWARPS];

    const int tid  = threadIdx.x;
    const int wid  = tid >> 5;
    const int lane = tid & 31;
    const int wr   = wid / 3;            // warp row-block 0..1
    const int wc   = wid % 3;            // warp col-block 0..2
    const int lr   = lane >> 2;          // row slot 0..7
    const int lc   = lane & 3;           // col slot 0..3
    const int r0   = wr * 24 + lr * 3;   // rows r0..r0+2
    const int c0   = wc * 16 + lc * 4;   // col block

    const float* yb  = y  + (size_t)blockIdx.x * NPIX;
    const float* ytb = yt + (size_t)blockIdx.x * NPIX;

    if (tid < NSIDE) {
        float dd = (float)tid * (1.0f / 48.0f);
        float d2 = dd * dd;
        float k  = expf(-d2 * INV_EPS);
        ktab[tid]  = k;
        kdtab[tid] = k * d2;
    }
    for (int i = tid; i < NPIX; i += NTHREADS) {
        int ro = i / NSIDE, co = i % NSIDE;
        int d  = ro - co; d = d < 0 ? -d : d;
        float dd = (float)d * (1.0f / 48.0f);
        float k  = expf(-dd * dd * INV_EPS);
        sK[ro * LDW + co] = k;
        sK2[ro * LDW2 + 2 * co]     = k;
        sK2[ro * LDW2 + 2 * co + 1] = k;
    }

    float sxl = 0.0f, syl = 0.0f;
    for (int i = tid; i < NPIX; i += NTHREADS) {
        sxl += mass_of(yb[i]);
        syl += mass_of(ytb[i]);
    }
    __syncthreads();
    const float sx = block_reduce(sxl, red);
    const float sy = block_reduce(syl, red);
    const float rsx = 1.0f / sx, rsy = 1.0f / sy;

    float4 mu4[3], nu4[3], a4[3], b4[3];
#pragma unroll
    for (int i = 0; i < 3; i++) {
        int gidx = (r0 + i) * NSIDE + c0;
        float4 yv  = ld4(yb  + gidx);
        float4 ytv = ld4(ytb + gidx);
        mu4[i] = make_float4(mass_of(yv.x) * rsx, mass_of(yv.y) * rsx,
                             mass_of(yv.z) * rsx, mass_of(yv.w) * rsx);
        nu4[i] = make_float4(mass_of(ytv.x) * rsy, mass_of(ytv.y) * rsy,
                             mass_of(ytv.z) * rsy, mass_of(ytv.w) * rsy);
        a4[i] = make_float4(1.f, 1.f, 1.f, 1.f);
        b4[i] = make_float4(1.f, 1.f, 1.f, 1.f);
        st4(&sA[(r0 + i) * LDW + c0], a4[i]);
        st4(&sB[(r0 + i) * LDW + c0], b4[i]);
    }
    __syncthreads();

    // 5 Sinkhorn iterations; u-update (h=0) and v-update (h=1) share one body.
    u64t t[3][2], s[3][2];
#pragma unroll 1
    for (int it = 0; it < 5; it++) {
#pragma unroll 1
        for (int h = 0; h < 2; h++) {
            const float* X = h ? sA : sB;    // operand (normal layout)
            float* D       = h ? sB : sA;    // destination scalings
            // mm1: T = K*X  (banded on warp row-block)
            if (wr == 0) mm_d<0, 10>(sK2, X, r0, c0, t);
            else         mm_d<2, 12>(sK2, X, r0, c0, t);
#pragma unroll
            for (int i = 0; i < 3; i++)
                st_doubled(&sT2[(r0 + i) * LDW2 + 2 * c0], t[i][0], t[i][1]);
            __syncthreads();
            // mm2: S = T*K  (banded on warp col-block)
            if      (wc == 0) mm_d<0, 8 >(sT2, sK, r0, c0, s);
            else if (wc == 1) mm_d<0, 12>(sT2, sK, r0, c0, s);
            else              mm_d<4, 12>(sT2, sK, r0, c0, s);
#pragma unroll
            for (int i = 0; i < 3; i++) {
                float4 mv = h ? nu4[i] : mu4[i];
                float4 xv = h ? b4[i]  : a4[i];
                float2 slo = unpack2(s[i][0]);
                float2 shi = unpack2(s[i][1]);
                float4 nx;
                nx.x = __fdividef(mv.x * xv.x, fmaf(xv.x, slo.x, 1e-6f));
                nx.y = __fdividef(mv.y * xv.y, fmaf(xv.y, slo.y, 1e-6f));
                nx.z = __fdividef(mv.z * xv.z, fmaf(xv.z, shi.x, 1e-6f));
                nx.w = __fdividef(mv.w * xv.w, fmaf(xv.w, shi.y, 1e-6f));
                if (h) b4[i] = nx; else a4[i] = nx;
                st4(&D[(r0 + i) * LDW + c0], nx);
            }
            __syncthreads();
        }
    }

    // cost = sum_i a_i * [ (KD*B*K) + (K*B*KD) ]_i  — 2 fused banded passes.
    float* sT = sT2;   // reuse doubled buffer as NORMAL-stride scratch
    {
        const int bl = (wr == 0) ? 0 : 8;
        const int bh = (wr == 0) ? 40 : 48;
        float4 t1[3], t2[3];
#pragma unroll
        for (int i = 0; i < 3; i++) {
            t1[i] = make_float4(0.f, 0.f, 0.f, 0.f);
            t2[i] = make_float4(0.f, 0.f, 0.f, 0.f);
        }
#pragma unroll 8
        for (int b = bl; b < bh; b++) {
            float4 bv = ld4(sB + b * LDW + c0);
#pragma unroll
            for (int i = 0; i < 3; i++) {
                int d0 = r0 + i - b; d0 = d0 < 0 ? -d0 : d0;
                float kd = kdtab[d0];
                float kk = ktab[d0];
                t1[i].x = fmaf(kd, bv.x, t1[i].x); t1[i].y = fmaf(kd, bv.y, t1[i].y);
                t1[i].z = fmaf(kd, bv.z, t1[i].z); t1[i].w = fmaf(kd, bv.w, t1[i].w);
                t2[i].x = fmaf(kk, bv.x, t2[i].x); t2[i].y = fmaf(kk, bv.y, t2[i].y);
                t2[i].z = fmaf(kk, bv.z, t2[i].z); t2[i].w = fmaf(kk, bv.w, t2[i].w);
            }
        }
        __syncthreads();
#pragma unroll
        for (int i = 0; i < 3; i++) {
            st4(&sT[(r0 + i) * LDW + c0], t1[i]);
            st4(&sA[(r0 + i) * LDW + c0], t2[i]);
        }
        __syncthreads();
    }

    float cl = 0.0f;
    {
        const int bl = (wc == 2) ? 16 : 0;
        const int bh = (wc == 0) ? 32 : 48;
        float4 s1[3], s2[3];
#pragma unroll
        for (int i = 0; i < 3; i++) {
            s1[i] = make_float4(0.f, 0.f, 0.f, 0.f);
            s2[i] = make_float4(0.f, 0.f, 0.f, 0.f);
        }
#pragma unroll 8
        for (int b = bl; b < bh; b++) {
            float4 kv = ld4(sK + b * LDW + c0);
            int e0 = b - c0;     e0 = e0 < 0 ? -e0 : e0;
            int e1 = b - c0 - 1; e1 = e1 < 0 ? -e1 : e1;
            int e2 = b - c0 - 2; e2 = e2 < 0 ? -e2 : e2;
            int e3 = b - c0 - 3; e3 = e3 < 0 ? -e3 : e3;
            float kd0 = kdtab[e0], kd1 = kdtab[e1], kd2 = kdtab[e2], kd3 = kdtab[e3];
#pragma unroll
            for (int i = 0; i < 3; i++) {
                float p0 = sT[(r0 + i) * LDW + b];
                float q0 = sA[(r0 + i) * LDW + b];
                s1[i].x = fmaf(p0, kv.x, s1[i].x); s1[i].y = fmaf(p0, kv.y, s1[i].y);
                s1[i].z = fmaf(p0, kv.z, s1[i].z); s1[i].w = fmaf(p0, kv.w, s1[i].w);
                s2[i].x = fmaf(q0, kd0, s2[i].x);  s2[i].y = fmaf(q0, kd1, s2[i].y);
                s2[i].z = fmaf(q0, kd2, s2[i].z);  s2[i].w = fmaf(q0, kd3, s2[i].w);
            }
        }
#pragma unroll
        for (int i = 0; i < 3; i++) {
            cl += a4[i].x * (s1[i].x + s2[i].x);
            cl += a4[i].y * (s1[i].y + s2[i].y);
            cl += a4[i].z * (s1[i].z + s2[i].z);
            cl += a4[i].w * (s1[i].w + s2[i].w);
        }
    }

    float c = block_reduce(cl, red);

    // last CTA finalizes the batch mean (counter self-resets: replay-safe)
    if (tid == 0) {
        g_cost[blockIdx.x] = c;
        __threadfence();
        unsigned done = atomicAdd(&g_count, 1u);
        if (done == (unsigned)(nb - 1)) {
            float ssum = 0.0f;
            for (int i = 0; i < nb; i++) ssum += g_cost[i];
            *out = ssum / (float)nb;
            g_count = 0;
        }
    }
}

extern "C" void kernel_launch(void* const* d_in, const int* in_sizes, int n_in,
                              void* d_out, int out_size) {
    const float* y  = (const float*)d_in[0];
    const float* yt = (const float*)d_in[1];
    float* out = (float*)d_out;

    int nb = in_sizes[0] / NPIX;   // 16
    if (nb < 1)    nb = 1;
    if (nb > MAXB) nb = MAXB;

    static bool attr_done = false;
    if (!attr_done) {
        cudaFuncSetAttribute(sinkhorn_kernel,
                             cudaFuncAttributeMaxDynamicSharedMemorySize,
                             DYN_BYTES);
        attr_done = true;
    }
    sinkhorn_kernel<<<nb, NTHREADS, DYN_BYTES>>>(y, yt, out, nb);
}